// round 1
// baseline (speedup 1.0000x reference)
#include <cuda_runtime.h>
#include <math.h>
#include <stdint.h>

// ---------------- problem constants ----------------
#define BB     64
#define HH     56
#define WW     56
#define CC     192
#define NHEADS 6
#define HD     32          // head dim
#define WSZ    7
#define TOK    49          // tokens per window
#define NWIN_I 64          // windows per image (8*8)
#define SHIFT  3
#define NTOK   (BB*HH*WW)  // 200704 tokens total
#define NWIN   (BB*NWIN_I) // 4096 windows total
#define HIDDEN 768

// ---------------- scratch (device globals; no allocs allowed) ----------------
__device__ float g_xw  [(size_t)NTOK*CC];      // LN1 + shift + window partition
__device__ float g_qkv [(size_t)NTOK*3*CC];    // qkv projection
__device__ float g_att [(size_t)NTOK*CC];      // attention output (window layout)
__device__ float g_proj[(size_t)NTOK*CC];      // after proj GEMM (window layout)
__device__ float g_x1  [(size_t)NTOK*CC];      // x + attn branch (image layout)
__device__ float g_ln2 [(size_t)NTOK*CC];      // LN2 output
__device__ float g_hid [(size_t)NTOK*HIDDEN];  // MLP hidden

// ---------------- helpers ----------------
__device__ __forceinline__ float warp_sum(float v) {
    #pragma unroll
    for (int o = 16; o > 0; o >>= 1) v += __shfl_xor_sync(0xffffffffu, v, o);
    return v;
}
__device__ __forceinline__ float warp_max(float v) {
    #pragma unroll
    for (int o = 16; o > 0; o >>= 1) v = fmaxf(v, __shfl_xor_sync(0xffffffffu, v, o));
    return v;
}
__device__ __forceinline__ float gelu_exact(float x) {
    return 0.5f * x * (1.0f + erff(x * 0.70710678118654752f));
}

// ---------------- LN1 + roll(-3,-3) + window partition ----------------
// one block per window-token, 192 threads (one per channel)
__global__ void k_ln1_shift_part(const float* __restrict__ x,
                                 const float* __restrict__ g,
                                 const float* __restrict__ b) {
    int w   = blockIdx.x;         // 0..NTOK-1 (window-token index)
    int c   = threadIdx.x;        // 0..191
    int n   = w / TOK, t = w % TOK;
    int img = n / NWIN_I, win = n % NWIN_I;
    int hs  = (win / 8) * WSZ + t / WSZ;     // shifted-coords pixel
    int ws  = (win % 8) * WSZ + t % WSZ;
    int hsrc = (hs + SHIFT) % HH;            // roll(-SHIFT): out[i] = in[(i+SHIFT)%H]
    int wsrc = (ws + SHIFT) % WW;
    const float* row = x + ((size_t)img * (HH*WW) + hsrc * WW + wsrc) * CC;

    float val = row[c];
    float s  = warp_sum(val);
    float s2 = warp_sum(val * val);
    __shared__ float sh1[6], sh2[6];
    int lane = c & 31, warp = c >> 5;
    if (lane == 0) { sh1[warp] = s; sh2[warp] = s2; }
    __syncthreads();
    float ts = 0.f, ts2 = 0.f;
    #pragma unroll
    for (int i = 0; i < 6; i++) { ts += sh1[i]; ts2 += sh2[i]; }
    float mean = ts * (1.0f / CC);
    float var  = ts2 * (1.0f / CC) - mean * mean;
    float inv  = rsqrtf(var + 1e-5f);
    g_xw[(size_t)w * CC + c] = (val - mean) * inv * g[c] + b[c];
}

// ---------------- plain LN (image layout) ----------------
__global__ void k_ln2(const float* __restrict__ x,
                      const float* __restrict__ g,
                      const float* __restrict__ b) {
    int tok = blockIdx.x;
    int c   = threadIdx.x;
    float val = x[(size_t)tok * CC + c];
    float s  = warp_sum(val);
    float s2 = warp_sum(val * val);
    __shared__ float sh1[6], sh2[6];
    int lane = c & 31, warp = c >> 5;
    if (lane == 0) { sh1[warp] = s; sh2[warp] = s2; }
    __syncthreads();
    float ts = 0.f, ts2 = 0.f;
    #pragma unroll
    for (int i = 0; i < 6; i++) { ts += sh1[i]; ts2 += sh2[i]; }
    float mean = ts * (1.0f / CC);
    float var  = ts2 * (1.0f / CC) - mean * mean;
    float inv  = rsqrtf(var + 1e-5f);
    g_ln2[(size_t)tok * CC + c] = (val - mean) * inv * g[c] + b[c];
}

// ---------------- tiled fp32 GEMM:  C[M,N] = A[M,K] @ W[N,K]^T + bias  ----------------
// BM=BN=64, BK=16, 256 threads, 4x4 micro-tile per thread.
// epi: 0 = none, 1 = gelu, 2 = add residual (res has same MxN layout)
__global__ void k_gemm(const float* __restrict__ A,
                       const float* __restrict__ Wt,
                       const float* __restrict__ bias,
                       const float* __restrict__ res,
                       float* __restrict__ Cmat,
                       int M, int N, int K, int epi) {
    __shared__ float As[64][17];
    __shared__ float Ws[64][17];

    int tid = threadIdx.x;                 // 0..255
    int tx = tid & 15, ty = tid >> 4;      // 16x16
    int gm0 = blockIdx.x * 64;
    int gn0 = blockIdx.y * 64;

    float acc[4][4];
    #pragma unroll
    for (int i = 0; i < 4; i++)
        #pragma unroll
        for (int j = 0; j < 4; j++) acc[i][j] = 0.f;

    int lm = tid >> 2;            // 0..63 (row within tile)
    int lk = (tid & 3) * 4;       // 0,4,8,12 (k offset)

    for (int k0 = 0; k0 < K; k0 += 16) {
        float4 av = *reinterpret_cast<const float4*>(A  + (size_t)(gm0 + lm) * K + k0 + lk);
        float4 wv = *reinterpret_cast<const float4*>(Wt + (size_t)(gn0 + lm) * K + k0 + lk);
        As[lm][lk+0] = av.x; As[lm][lk+1] = av.y; As[lm][lk+2] = av.z; As[lm][lk+3] = av.w;
        Ws[lm][lk+0] = wv.x; Ws[lm][lk+1] = wv.y; Ws[lm][lk+2] = wv.z; Ws[lm][lk+3] = wv.w;
        __syncthreads();
        #pragma unroll
        for (int kk = 0; kk < 16; kk++) {
            float a[4], w[4];
            #pragma unroll
            for (int i = 0; i < 4; i++) a[i] = As[ty*4 + i][kk];
            #pragma unroll
            for (int j = 0; j < 4; j++) w[j] = Ws[tx*4 + j][kk];
            #pragma unroll
            for (int i = 0; i < 4; i++)
                #pragma unroll
                for (int j = 0; j < 4; j++) acc[i][j] = fmaf(a[i], w[j], acc[i][j]);
        }
        __syncthreads();
    }

    #pragma unroll
    for (int i = 0; i < 4; i++) {
        int m = gm0 + ty*4 + i;
        #pragma unroll
        for (int j = 0; j < 4; j++) {
            int nn = gn0 + tx*4 + j;
            float v = acc[i][j] + bias[nn];
            if (epi == 1)      v = gelu_exact(v);
            else if (epi == 2) v += res[(size_t)m * N + nn];
            Cmat[(size_t)m * N + nn] = v;
        }
    }
}

// ---------------- windowed attention: one block per (window, head) ----------------
__global__ void k_attn(const float* __restrict__ rpb,
                       const int*   __restrict__ relidx,
                       const float* __restrict__ amask) {
    int blk = blockIdx.x;
    int n = blk / NHEADS, h = blk % NHEADS;
    int win = n % NWIN_I;

    __shared__ float sq[TOK][HD], sk[TOK][HD], sv[TOK][HD];
    __shared__ float sp[4][TOK + 3];

    const float* base = g_qkv + (size_t)n * TOK * (3*CC);
    int tid = threadIdx.x;
    const float scale = 0.17677669529663687f;   // 1/sqrt(32)
    for (int i = tid; i < TOK * HD; i += 128) {
        int t = i / HD, d = i % HD;
        sq[t][d] = base[t*(3*CC) +        h*HD + d] * scale;
        sk[t][d] = base[t*(3*CC) + CC   + h*HD + d];
        sv[t][d] = base[t*(3*CC) + 2*CC + h*HD + d];
    }
    __syncthreads();

    int warp = tid >> 5, lane = tid & 31;
    const float* mrow = amask + (size_t)win * TOK * TOK;

    for (int r = warp; r < TOK; r += 4) {
        float s0 = -1e30f, s1 = -1e30f;
        {
            float a = 0.f;
            #pragma unroll
            for (int d = 0; d < HD; d++) a = fmaf(sq[r][d], sk[lane][d], a);
            a += rpb[relidx[r*TOK + lane] * NHEADS + h] + mrow[r*TOK + lane];
            s0 = a;
        }
        int t2 = lane + 32;
        if (t2 < TOK) {
            float a = 0.f;
            #pragma unroll
            for (int d = 0; d < HD; d++) a = fmaf(sq[r][d], sk[t2][d], a);
            a += rpb[relidx[r*TOK + t2] * NHEADS + h] + mrow[r*TOK + t2];
            s1 = a;
        }
        float mx = warp_max(fmaxf(s0, s1));
        float p0 = __expf(s0 - mx);
        float p1 = (t2 < TOK) ? __expf(s1 - mx) : 0.f;
        float sum = warp_sum(p0 + p1);
        float inv = 1.0f / sum;
        sp[warp][lane] = p0 * inv;
        if (t2 < TOK) sp[warp][t2] = p1 * inv;
        __syncwarp();

        // out[r][d], d = lane (HD == 32)
        float o = 0.f;
        #pragma unroll
        for (int t = 0; t < TOK; t++) o = fmaf(sp[warp][t], sv[t][lane], o);
        g_att[((size_t)n * TOK + r) * CC + h*HD + lane] = o;
        __syncwarp();
    }
}

// ---------------- window reverse + roll(+3,+3) + residual add ----------------
__global__ void k_resid(const float* __restrict__ x) {
    size_t i = (size_t)blockIdx.x * blockDim.x + threadIdx.x;
    if (i >= (size_t)NTOK * CC) return;
    int c = (int)(i % CC);
    size_t tok = i / CC;
    int img = (int)(tok / (HH*WW));
    int hw  = (int)(tok % (HH*WW));
    int hh = hw / WW, ww = hw % WW;
    int hs = (hh + HH - SHIFT) % HH;    // inverse of roll(+SHIFT)
    int ws = (ww + WW - SHIFT) % WW;
    int win = (hs / WSZ) * 8 + (ws / WSZ);
    int t   = (hs % WSZ) * WSZ + (ws % WSZ);
    size_t widx = ((size_t)(img * NWIN_I + win) * TOK + t) * CC + c;
    g_x1[i] = x[i] + g_proj[widx];
}

// ---------------- launch ----------------
extern "C" void kernel_launch(void* const* d_in, const int* in_sizes, int n_in,
                              void* d_out, int out_size) {
    const float* x       = (const float*)d_in[0];
    const float* norm1_g = (const float*)d_in[1];
    const float* norm1_b = (const float*)d_in[2];
    const float* qkv_w   = (const float*)d_in[3];
    const float* qkv_b   = (const float*)d_in[4];
    const float* rpb     = (const float*)d_in[5];
    const float* proj_w  = (const float*)d_in[6];
    const float* proj_b  = (const float*)d_in[7];
    const float* norm2_g = (const float*)d_in[8];
    const float* norm2_b = (const float*)d_in[9];
    const float* fc1_w   = (const float*)d_in[10];
    const float* fc1_b   = (const float*)d_in[11];
    const float* fc2_w   = (const float*)d_in[12];
    const float* fc2_b   = (const float*)d_in[13];
    // dict order vs signature order ambiguity: disambiguate by element count
    const int*   relidx;
    const float* amask;
    if (in_sizes[14] == TOK * TOK) {
        relidx = (const int*)d_in[14];  amask = (const float*)d_in[15];
    } else {
        relidx = (const int*)d_in[15];  amask = (const float*)d_in[14];
    }
    float* out = (float*)d_out;

    float *p_xw, *p_qkv, *p_att, *p_proj, *p_x1, *p_ln2, *p_hid;
    cudaGetSymbolAddress((void**)&p_xw,   g_xw);
    cudaGetSymbolAddress((void**)&p_qkv,  g_qkv);
    cudaGetSymbolAddress((void**)&p_att,  g_att);
    cudaGetSymbolAddress((void**)&p_proj, g_proj);
    cudaGetSymbolAddress((void**)&p_x1,   g_x1);
    cudaGetSymbolAddress((void**)&p_ln2,  g_ln2);
    cudaGetSymbolAddress((void**)&p_hid,  g_hid);

    // 1) LN1 + shift + window partition
    k_ln1_shift_part<<<NTOK, CC>>>(x, norm1_g, norm1_b);

    // 2) qkv GEMM: (NTOK,192) @ (576,192)^T
    {
        dim3 grid(NTOK/64, (3*CC)/64);
        k_gemm<<<grid, 256>>>(p_xw, qkv_w, qkv_b, nullptr, p_qkv, NTOK, 3*CC, CC, 0);
    }

    // 3) windowed attention
    k_attn<<<NWIN * NHEADS, 128>>>(rpb, relidx, amask);

    // 4) proj GEMM
    {
        dim3 grid(NTOK/64, CC/64);
        k_gemm<<<grid, 256>>>(p_att, proj_w, proj_b, nullptr, p_proj, NTOK, CC, CC, 0);
    }

    // 5) window reverse + roll back + residual
    {
        size_t total = (size_t)NTOK * CC;
        int threads = 256;
        int blocks = (int)((total + threads - 1) / threads);
        k_resid<<<blocks, threads>>>(x);
    }

    // 6) LN2
    k_ln2<<<NTOK, CC>>>(p_x1, norm2_g, norm2_b);

    // 7) fc1 + GELU
    {
        dim3 grid(NTOK/64, HIDDEN/64);
        k_gemm<<<grid, 256>>>(p_ln2, fc1_w, fc1_b, nullptr, p_hid, NTOK, HIDDEN, CC, 1);
    }

    // 8) fc2 + residual -> d_out
    {
        dim3 grid(NTOK/64, CC/64);
        k_gemm<<<grid, 256>>>(p_hid, fc2_w, fc2_b, p_x1, out, NTOK, CC, HIDDEN, 2);
    }
}